// round 14
// baseline (speedup 1.0000x reference)
#include <cuda_runtime.h>
#include <cuda_fp16.h>
#include <cstdint>

typedef unsigned long long u64;

#define E_CNT 100000
#define NDST  10000
#define OUTC  2048

// ---------------- small device scratch (CSR only) ----------------
__device__ int g_counts[NDST];
__device__ int g_cursor[NDST];
__device__ int g_eid   [E_CNT];

// ---------------- prologue kernels ----------------
__global__ void zero_cnt_k() {
    int i = blockIdx.x * blockDim.x + threadIdx.x;
    if (i < NDST) g_counts[i] = 0;
}
__global__ void hist_k(const int* __restrict__ dst) {
    int e = blockIdx.x * blockDim.x + threadIdx.x;
    if (e < E_CNT) atomicAdd(&g_counts[dst[e]], 1);
}
__global__ void scan_k() {
    __shared__ int ss[1024];
    const int tid = threadIdx.x;
    const int CH = 10;
    int base = tid * CH, loc[CH], s = 0;
#pragma unroll
    for (int i = 0; i < CH; i++) {
        int idx = base + i;
        int v = (idx < NDST) ? g_counts[idx] : 0;
        loc[i] = s; s += v;
    }
    ss[tid] = s; __syncthreads();
    for (int off = 1; off < 1024; off <<= 1) {
        int v = 0;
        if (tid >= off) v = ss[tid - off];
        __syncthreads();
        if (tid >= off) ss[tid] += v;
        __syncthreads();
    }
    int excl = (tid == 0) ? 0 : ss[tid - 1];
#pragma unroll
    for (int i = 0; i < CH; i++) {
        int idx = base + i;
        if (idx < NDST) g_cursor[idx] = excl + loc[i];
    }
}
__global__ void fill_k(const int* __restrict__ dst) {
    int e = blockIdx.x * blockDim.x + threadIdx.x;
    if (e < E_CNT) {
        int p = atomicAdd(&g_cursor[dst[e]], 1);
        g_eid[p] = e;
    }
}
__global__ void zero_out_k(float4* __restrict__ out, int n4) {
    int i = blockIdx.x * blockDim.x + threadIdx.x;
    if (i < n4) out[i] = make_float4(0.f, 0.f, 0.f, 0.f);
}

// ---------------- helpers ----------------
__device__ __forceinline__ void ffma2(u64& d, u64 a, u64 b) {
    asm("fma.rn.f32x2 %0, %1, %2, %0;" : "+l"(d) : "l"(a), "l"(b));
}
__device__ __forceinline__ u64 pack2(float x) {
    u64 r; asm("mov.b64 %0, {%1, %1};" : "=l"(r) : "f"(x)); return r;
}
__device__ __forceinline__ u64 packf2(float lo, float hi) {
    u64 r; asm("mov.b64 %0, {%1, %2};" : "=l"(r) : "f"(lo), "f"(hi)); return r;
}
__device__ __forceinline__ float2 unpack2(u64 v) {
    float2 f; asm("mov.b64 {%0, %1}, %2;" : "=f"(f.x), "=f"(f.y) : "l"(v)); return f;
}
__device__ __forceinline__ float silu_f(float x) {
    return x / (1.f + __expf(-x));
}
__device__ __forceinline__ void mma16(float* c, uint32_t a0, uint32_t a1,
                                      uint32_t a2, uint32_t a3,
                                      uint32_t b0, uint32_t b1) {
    asm("mma.sync.aligned.m16n8k16.row.col.f32.f16.f16.f32 "
        "{%0,%1,%2,%3}, {%4,%5,%6,%7}, {%8,%9}, {%0,%1,%2,%3};"
        : "+f"(c[0]), "+f"(c[1]), "+f"(c[2]), "+f"(c[3])
        : "r"(a0), "r"(a1), "r"(a2), "r"(a3), "r"(b0), "r"(b1));
}

// ---------------- smem layouts ----------------
// Path A (FFMA2, R10): floats  Hst[128][66] | Ws[64][128] (EMBt alias) |
//                      W1s[64][128] (TPW alias) | SHs[64][16] | ints
#define FA_HST  0
#define FA_WS   8448
#define FA_W1S  16640
#define FA_SHS  24832
#define FA_END  25856
#define A_BYTES ((FA_END + 192) * 4)           // 104192
// Path B (fp16 mma, R9): bytes Hs[64][136] | WT[128][72] | TPW f[64][128]
//                        (As h[64][72] alias) | SHs f[64][16] | ints
#define FB_HS    0
#define FB_WT    17408
#define FB_TPW   35840
#define FB_SHS   68608
#define FB_INTS  72704
#define B_BYTES  (FB_INTS + 192 * 4)           // 73472
#define SMEM_BYTES A_BYTES

// =================== Path A: FFMA2 (exact R10 hot path) ====================
__device__ void path_ffma2(
    char* smc, int tile,
    const float* __restrict__ src_features, const float* __restrict__ edge_sh,
    const float* __restrict__ edge_emb, const float* __restrict__ W1,
    const float* __restrict__ W2, const int* __restrict__ src,
    const int* __restrict__ dst, float* __restrict__ out)
{
    float* sm   = (float*)smc;
    float* Hst  = sm + FA_HST;
    float* Ws   = sm + FA_WS;   float* EMBt = Ws;
    float* W1s  = sm + FA_W1S;  float* TPW  = W1s;
    float* SHs  = sm + FA_SHS;
    int*   Es   = (int*)(sm + FA_END);
    int*   Ss   = Es + 64;
    int*   Ds   = Ss + 64;

    const int tid = threadIdx.x;
    const int tr  = tid >> 5;
    const int r0  = tr * 8;
    const int c0  = (tid & 31) * 4;

    const int pos0 = tile * 64;
    const int nE   = (E_CNT - pos0 < 64) ? (E_CNT - pos0) : 64;
    if (tid < 64) {
        int sl = (tid < nE) ? tid : (nE - 1);
        int e  = g_eid[pos0 + sl];
        Es[tid] = e; Ss[tid] = src[e]; Ds[tid] = dst[e];
    }
    __syncthreads();

#pragma unroll
    for (int it = 0; it < 4; it++) {
        int li = tid + it * 256;
        int slot = li >> 4, f = li & 15;
        float4 v = *(const float4*)&edge_emb[(size_t)Es[slot] * 64 + f * 4];
        EMBt[(f * 4 + 0) * 66 + slot] = v.x;
        EMBt[(f * 4 + 1) * 66 + slot] = v.y;
        EMBt[(f * 4 + 2) * 66 + slot] = v.z;
        EMBt[(f * 4 + 3) * 66 + slot] = v.w;
    }
#pragma unroll
    for (int it = 0; it < 8; it++) {
        int li = tid + it * 256;
        int k = li >> 5, f = li & 31;
        float4 v = *(const float4*)&W1[(size_t)k * 128 + f * 4];
        v.x *= 0.125f; v.y *= 0.125f; v.z *= 0.125f; v.w *= 0.125f;
        *(float4*)&W1s[k * 128 + f * 4] = v;
    }
    {
        int slot = tid >> 2, j = tid & 3;
        float4 v = make_float4(0.f, 0.f, 0.f, 0.f);
        if (slot < nE)
            v = *(const float4*)&edge_sh[(size_t)Es[slot] * 16 + j * 4];
        *(float4*)&SHs[slot * 16 + j * 4] = v;
    }
    __syncthreads();

    {
        u64 acc[4][4];
#pragma unroll
        for (int p = 0; p < 4; p++)
#pragma unroll
            for (int j = 0; j < 4; j++) acc[p][j] = 0ull;
#pragma unroll 8
        for (int kk = 0; kk < 64; kk++) {
            float4 rb = *(const float4*)&W1s[kk * 128 + c0];
            u64 bb0 = pack2(rb.x), bb1 = pack2(rb.y);
            u64 bb2 = pack2(rb.z), bb3 = pack2(rb.w);
#pragma unroll
            for (int p = 0; p < 4; p++) {
                u64 ap = *(const u64*)&EMBt[kk * 66 + r0 + 2 * p];
                ffma2(acc[p][0], ap, bb0); ffma2(acc[p][1], ap, bb1);
                ffma2(acc[p][2], ap, bb2); ffma2(acc[p][3], ap, bb3);
            }
        }
#pragma unroll
        for (int p = 0; p < 4; p++)
#pragma unroll
            for (int j = 0; j < 4; j++) {
                float2 v = unpack2(acc[p][j]);
                v.x = silu_f(v.x); v.y = silu_f(v.y);
                *(u64*)&Hst[(c0 + j) * 66 + r0 + 2 * p] = packf2(v.x, v.y);
            }
    }
    __syncthreads();

    const float w2s = 0.08838834764831845f;
    for (int l = 0; l < 4; l++) {
        u64 acc[4][4];
#pragma unroll
        for (int p = 0; p < 4; p++)
#pragma unroll
            for (int j = 0; j < 4; j++) acc[p][j] = 0ull;

        for (int k0 = 0; k0 < 128; k0 += 64) {
            if (k0) __syncthreads();
#pragma unroll
            for (int it = 0; it < 8; it++) {
                int li = tid + it * 256;
                int k = li >> 5, f = li & 31;
                float4 v = *(const float4*)&W2[(size_t)(k0 + k) * 512 + l * 128 + f * 4];
                v.x *= w2s; v.y *= w2s; v.z *= w2s; v.w *= w2s;
                *(float4*)&Ws[k * 128 + f * 4] = v;
            }
            __syncthreads();
#pragma unroll 8
            for (int kk = 0; kk < 64; kk++) {
                float4 rb = *(const float4*)&Ws[kk * 128 + c0];
                u64 bb0 = pack2(rb.x), bb1 = pack2(rb.y);
                u64 bb2 = pack2(rb.z), bb3 = pack2(rb.w);
#pragma unroll
                for (int p = 0; p < 4; p++) {
                    u64 ap = *(const u64*)&Hst[(k0 + kk) * 66 + r0 + 2 * p];
                    ffma2(acc[p][0], ap, bb0); ffma2(acc[p][1], ap, bb1);
                    ffma2(acc[p][2], ap, bb2); ffma2(acc[p][3], ap, bb3);
                }
            }
        }
        __syncthreads();

#pragma unroll
        for (int p = 0; p < 4; p++) {
            int rA = r0 + 2 * p, rB = rA + 1;
            float4 xA = *(const float4*)&src_features[(size_t)Ss[rA] * 128 + c0];
            float4 xB = *(const float4*)&src_features[(size_t)Ss[rB] * 128 + c0];
            float2 q0 = unpack2(acc[p][0]), q1 = unpack2(acc[p][1]);
            float2 q2 = unpack2(acc[p][2]), q3 = unpack2(acc[p][3]);
            *(float4*)&TPW[rA * 128 + c0] =
                make_float4(q0.x * xA.x, q1.x * xA.y, q2.x * xA.z, q3.x * xA.w);
            *(float4*)&TPW[rB * 128 + c0] =
                make_float4(q0.y * xB.x, q1.y * xB.y, q2.y * xB.z, q3.y * xB.w);
        }
        __syncthreads();

        {
            const int d    = 2 * l + 1;
            const int soff = l * l;
            const int ob   = (l == 0) ? 0 : (l == 1) ? 128 : (l == 2) ? 512 : 1152;
            const int ncol = 128 * d;
            for (int q = tid; q < ncol; q += 256) {
                const int c = q / d;
                const int s = q - c * d;
                float a = 0.f;
                int cur = Ds[0];
#pragma unroll 8
                for (int e = 0; e < 64; e++) {
                    int dn = Ds[e];
                    if (dn != cur) {
                        atomicAdd(&out[(size_t)cur * OUTC + ob + q], a);
                        a = 0.f; cur = dn;
                    }
                    a += TPW[e * 128 + c] * SHs[e * 16 + soff + s];
                }
                atomicAdd(&out[(size_t)cur * OUTC + ob + q], a);
            }
        }
        __syncthreads();
    }
}

// =================== Path B: fp16 mma.sync (exact R9) ======================
__device__ void path_fp16(
    char* smc, int tile,
    const float* __restrict__ src_features, const float* __restrict__ edge_sh,
    const float* __restrict__ edge_emb, const float* __restrict__ W1,
    const float* __restrict__ W2, const int* __restrict__ src,
    const int* __restrict__ dst, float* __restrict__ out)
{
    __half* Hs  = (__half*)(smc + FB_HS);
    __half* WT  = (__half*)(smc + FB_WT);
    float*  TPW = (float*) (smc + FB_TPW);
    __half* As  = (__half*)(smc + FB_TPW);
    float*  SHs = (float*) (smc + FB_SHS);
    int*    Es  = (int*)   (smc + FB_INTS);
    int*    Ss  = Es + 64;
    int*    Ds  = Ss + 64;

    const int tid = threadIdx.x;
    const int w   = tid >> 5;
    const int t   = tid & 31;
    const int gp  = t >> 2;
    const int tg  = t & 3;
    const int r0  = (w & 3) * 16;
    const int n0  = (w >> 2) * 64;

    const int pos0 = tile * 64;
    const int nE   = (E_CNT - pos0 < 64) ? (E_CNT - pos0) : 64;
    if (tid < 64) {
        int sl = (tid < nE) ? tid : (nE - 1);
        int e  = g_eid[pos0 + sl];
        Es[tid] = e; Ss[tid] = src[e]; Ds[tid] = dst[e];
    }
    __syncthreads();

#pragma unroll
    for (int it = 0; it < 4; it++) {
        int li = tid + it * 256;
        int slot = li >> 4, f = li & 15;
        float4 v = *(const float4*)&edge_emb[(size_t)Es[slot] * 64 + f * 4];
        __half2* p = (__half2*)&As[slot * 72 + f * 4];
        p[0] = __floats2half2_rn(v.x, v.y);
        p[1] = __floats2half2_rn(v.z, v.w);
    }
#pragma unroll
    for (int it = 0; it < 8; it++) {
        int li = tid + it * 256;
        int k = li >> 5, n4 = (li & 31) * 4;
        float4 v = *(const float4*)&W1[(size_t)k * 128 + n4];
        WT[(n4 + 0) * 72 + k] = __float2half_rn(v.x * 0.125f);
        WT[(n4 + 1) * 72 + k] = __float2half_rn(v.y * 0.125f);
        WT[(n4 + 2) * 72 + k] = __float2half_rn(v.z * 0.125f);
        WT[(n4 + 3) * 72 + k] = __float2half_rn(v.w * 0.125f);
    }
    {
        int slot = tid >> 2, j = tid & 3;
        float4 v = make_float4(0.f, 0.f, 0.f, 0.f);
        if (slot < nE)
            v = *(const float4*)&edge_sh[(size_t)Es[slot] * 16 + j * 4];
        *(float4*)&SHs[slot * 16 + j * 4] = v;
    }
    __syncthreads();

    {
        float acc[8][4];
#pragma unroll
        for (int j = 0; j < 8; j++)
#pragma unroll
            for (int q = 0; q < 4; q++) acc[j][q] = 0.f;
#pragma unroll
        for (int k0 = 0; k0 < 64; k0 += 16) {
            uint32_t a0 = *(uint32_t*)&As[(r0 + gp)     * 72 + k0 + 2 * tg];
            uint32_t a1 = *(uint32_t*)&As[(r0 + gp + 8) * 72 + k0 + 2 * tg];
            uint32_t a2 = *(uint32_t*)&As[(r0 + gp)     * 72 + k0 + 2 * tg + 8];
            uint32_t a3 = *(uint32_t*)&As[(r0 + gp + 8) * 72 + k0 + 2 * tg + 8];
#pragma unroll
            for (int j = 0; j < 8; j++) {
                const __half* bp = &WT[(n0 + j * 8 + gp) * 72 + k0 + 2 * tg];
                uint32_t b0 = *(uint32_t*)bp;
                uint32_t b1 = *(uint32_t*)(bp + 8);
                mma16(acc[j], a0, a1, a2, a3, b0, b1);
            }
        }
#pragma unroll
        for (int j = 0; j < 8; j++) {
            int c = n0 + j * 8 + 2 * tg;
            int rA = r0 + gp, rB = r0 + gp + 8;
            float x0 = acc[j][0], x1 = acc[j][1], x2 = acc[j][2], x3 = acc[j][3];
            x0 = silu_f(x0); x1 = silu_f(x1); x2 = silu_f(x2); x3 = silu_f(x3);
            *(__half2*)&Hs[rA * 136 + c] = __floats2half2_rn(x0, x1);
            *(__half2*)&Hs[rB * 136 + c] = __floats2half2_rn(x2, x3);
        }
    }
    __syncthreads();

    const float w2s = 0.08838834764831845f;
    for (int l = 0; l < 4; l++) {
        float acc[8][4];
#pragma unroll
        for (int j = 0; j < 8; j++)
#pragma unroll
            for (int q = 0; q < 4; q++) acc[j][q] = 0.f;

#pragma unroll
        for (int kh = 0; kh < 2; kh++) {
            __syncthreads();
#pragma unroll
            for (int it = 0; it < 8; it++) {
                int li = tid + it * 256;
                int k = li >> 5, n4 = (li & 31) * 4;
                float4 v = *(const float4*)&W2[(size_t)(kh * 64 + k) * 512 + l * 128 + n4];
                WT[(n4 + 0) * 72 + k] = __float2half_rn(v.x * w2s);
                WT[(n4 + 1) * 72 + k] = __float2half_rn(v.y * w2s);
                WT[(n4 + 2) * 72 + k] = __float2half_rn(v.z * w2s);
                WT[(n4 + 3) * 72 + k] = __float2half_rn(v.w * w2s);
            }
            __syncthreads();
#pragma unroll
            for (int k0 = 0; k0 < 64; k0 += 16) {
                int kk = kh * 64 + k0;
                uint32_t a0 = *(uint32_t*)&Hs[(r0 + gp)     * 136 + kk + 2 * tg];
                uint32_t a1 = *(uint32_t*)&Hs[(r0 + gp + 8) * 136 + kk + 2 * tg];
                uint32_t a2 = *(uint32_t*)&Hs[(r0 + gp)     * 136 + kk + 2 * tg + 8];
                uint32_t a3 = *(uint32_t*)&Hs[(r0 + gp + 8) * 136 + kk + 2 * tg + 8];
#pragma unroll
                for (int j = 0; j < 8; j++) {
                    const __half* bp = &WT[(n0 + j * 8 + gp) * 72 + k0 + 2 * tg];
                    uint32_t b0 = *(uint32_t*)bp;
                    uint32_t b1 = *(uint32_t*)(bp + 8);
                    mma16(acc[j], a0, a1, a2, a3, b0, b1);
                }
            }
        }
        __syncthreads();

#pragma unroll
        for (int j = 0; j < 8; j++) {
            int c = n0 + j * 8 + 2 * tg;
            int rA = r0 + gp, rB = r0 + gp + 8;
            float2 xA = *(const float2*)&src_features[(size_t)Ss[rA] * 128 + c];
            float2 xB = *(const float2*)&src_features[(size_t)Ss[rB] * 128 + c];
            *(float2*)&TPW[rA * 128 + c] = make_float2(acc[j][0] * xA.x, acc[j][1] * xA.y);
            *(float2*)&TPW[rB * 128 + c] = make_float2(acc[j][2] * xB.x, acc[j][3] * xB.y);
        }
        __syncthreads();

        {
            const int d    = 2 * l + 1;
            const int soff = l * l;
            const int ob   = (l == 0) ? 0 : (l == 1) ? 128 : (l == 2) ? 512 : 1152;
            const int ncol = 128 * d;
            for (int q = tid; q < ncol; q += 256) {
                const int c = q / d;
                const int s = q - c * d;
                float a = 0.f;
                int cur = Ds[0];
#pragma unroll 8
                for (int e = 0; e < 64; e++) {
                    int dn = Ds[e];
                    if (dn != cur) {
                        atomicAdd(&out[(size_t)cur * OUTC + ob + q], a);
                        a = 0.f; cur = dn;
                    }
                    a += TPW[e * 128 + c] * SHs[e * 16 + soff + s];
                }
                atomicAdd(&out[(size_t)cur * OUTC + ob + q], a);
            }
        }
        __syncthreads();
    }
}

// =================== dispatcher: mix pipes per SM ==========================
__global__ __launch_bounds__(256, 2) void fused_k(
    const float* __restrict__ src_features,
    const float* __restrict__ edge_sh,
    const float* __restrict__ edge_emb,
    const float* __restrict__ W1,
    const float* __restrict__ W2,
    const int*   __restrict__ src,
    const int*   __restrict__ dst,
    float*       __restrict__ out)
{
    extern __shared__ char smc[];
    // bids b and b+148 land on the same SM (classic LUT on bid%148, occ 2):
    // (bid/148)&1 gives that SM one FFMA2 CTA and one fp16-MMA CTA.
    if (((blockIdx.x / 148) & 1) == 0)
        path_ffma2(smc, blockIdx.x, src_features, edge_sh, edge_emb,
                   W1, W2, src, dst, out);
    else
        path_fp16(smc, blockIdx.x, src_features, edge_sh, edge_emb,
                  W1, W2, src, dst, out);
}

// ---------------- launch ----------------
extern "C" void kernel_launch(void* const* d_in, const int* in_sizes, int n_in,
                              void* d_out, int out_size)
{
    const float* src_features = (const float*)d_in[0];
    const float* edge_sh      = (const float*)d_in[1];
    const float* edge_emb     = (const float*)d_in[2];
    const float* W1           = (const float*)d_in[3];
    const float* W2           = (const float*)d_in[4];
    const int*   src          = (const int*)d_in[5];
    const int*   dst          = (const int*)d_in[6];
    float*       out          = (float*)d_out;
    (void)in_sizes; (void)n_in; (void)out_size;

    static bool attr_done = false;
    if (!attr_done) {
        cudaFuncSetAttribute(fused_k, cudaFuncAttributeMaxDynamicSharedMemorySize,
                             SMEM_BYTES);
        attr_done = true;
    }

    // CSR build
    zero_cnt_k<<<(NDST + 255) / 256, 256>>>();
    hist_k<<<(E_CNT + 255) / 256, 256>>>(dst);
    scan_k<<<1, 1024>>>();
    fill_k<<<(E_CNT + 255) / 256, 256>>>(dst);

    // zero output (atomic accumulation target)
    const int n4 = NDST * OUTC / 4;
    zero_out_k<<<(n4 + 255) / 256, 256>>>((float4*)out, n4);

    // fused dual-pipe MLP + TP + scatter (64 edges/block, 2 CTAs/SM)
    const int nblk = (E_CNT + 63) / 64;
    fused_k<<<nblk, 256, SMEM_BYTES>>>(src_features, edge_sh, edge_emb,
                                       W1, W2, src, dst, out);
}

// round 16
// speedup vs baseline: 1.6715x; 1.6715x over previous
#include <cuda_runtime.h>
#include <cuda_fp16.h>
#include <cstdint>

typedef unsigned long long u64;
typedef unsigned int u32;

#define E_CNT 100000
#define NDST  10000
#define OUTC  2048

// ---------------- small device scratch (CSR only) ----------------
__device__ int g_counts[NDST];
__device__ int g_cursor[NDST];
__device__ int g_eid   [E_CNT];

// ---------------- prologue kernels ----------------
__global__ void zero_cnt_k() {
    int i = blockIdx.x * blockDim.x + threadIdx.x;
    if (i < NDST) g_counts[i] = 0;
}
__global__ void hist_k(const int* __restrict__ dst) {
    int e = blockIdx.x * blockDim.x + threadIdx.x;
    if (e < E_CNT) atomicAdd(&g_counts[dst[e]], 1);
}
__global__ void scan_k() {
    __shared__ int ss[1024];
    const int tid = threadIdx.x;
    const int CH = 10;
    int base = tid * CH, loc[CH], s = 0;
#pragma unroll
    for (int i = 0; i < CH; i++) {
        int idx = base + i;
        int v = (idx < NDST) ? g_counts[idx] : 0;
        loc[i] = s; s += v;
    }
    ss[tid] = s; __syncthreads();
    for (int off = 1; off < 1024; off <<= 1) {
        int v = 0;
        if (tid >= off) v = ss[tid - off];
        __syncthreads();
        if (tid >= off) ss[tid] += v;
        __syncthreads();
    }
    int excl = (tid == 0) ? 0 : ss[tid - 1];
#pragma unroll
    for (int i = 0; i < CH; i++) {
        int idx = base + i;
        if (idx < NDST) g_cursor[idx] = excl + loc[i];
    }
}
__global__ void fill_k(const int* __restrict__ dst) {
    int e = blockIdx.x * blockDim.x + threadIdx.x;
    if (e < E_CNT) {
        int p = atomicAdd(&g_cursor[dst[e]], 1);
        g_eid[p] = e;
    }
}
__global__ void zero_out_k(float4* __restrict__ out, int n4) {
    int i = blockIdx.x * blockDim.x + threadIdx.x;
    if (i < n4) out[i] = make_float4(0.f, 0.f, 0.f, 0.f);
}

__device__ __forceinline__ float silu_f(float x) {
    return x / (1.f + __expf(-x));
}
// half2 bits -> u32 (defined BEFORE use this time)
__device__ __forceinline__ u32 h2_bits(__half2 h) {
    return *(u32*)&h;
}

// ---------------- smem layout (byte offsets) ----------------
// Hsth u32[128][36] 18432 | Wsh u32[64][128] 32768 (EMBh half[64][72] alias) |
// W1sh u32[64][128] 32768 (TPW f[64][128] alias) | SHs f[64][16] 4096 | ints
#define B_HST  0
#define B_WS   18432
#define B_W1S  51200
#define B_SHS  83968
#define B_INT  88064
#define SMEM_BYTES (B_INT + 192 * 4)

// ---------------- fused kernel: HFMA2 MLP + TP + segment scatter -----------
__global__ __launch_bounds__(256, 2) void fused_k(
    const float* __restrict__ src_features,
    const float* __restrict__ edge_sh,
    const float* __restrict__ edge_emb,
    const float* __restrict__ W1,
    const float* __restrict__ W2,
    const int*   __restrict__ src,
    const int*   __restrict__ dst,
    float*       __restrict__ out)
{
    extern __shared__ char smc[];
    u32*    Hsth = (u32*)(smc + B_HST);    // [k=128][pair 32 + 4pad] half2 words
    u32*    Wsh  = (u32*)(smc + B_WS);     // [k=64][n 128] dup half2
    __half* EMBh = (__half*)(smc + B_WS);  // [k=64][row 72] halves (alias)
    u32*    EMBw = (u32*)(smc + B_WS);     // same, word view (pair access)
    u32*    W1sh = (u32*)(smc + B_W1S);    // [k=64][n 128] dup half2
    float*  TPW  = (float*)(smc + B_W1S);  // [row 64][c 128] alias
    float*  SHs  = (float*)(smc + B_SHS);  // [row 64][16]
    int*    Es   = (int*)(smc + B_INT);
    int*    Ss   = Es + 64;
    int*    Ds   = Ss + 64;

    const int tid = threadIdx.x;
    const int tr  = tid >> 5;     // warp 0..7 -> rows tr*8..tr*8+7 (pairs tr*4..+3)
    const int tc  = tid & 31;
    const int p0  = tr * 4;       // pair base
    const int r0  = tr * 8;
    const int c0  = tc * 4;       // 4 cols per lane

    // ---- stage edge metadata (pads replicate last edge; SH pads -> 0) ----
    const int pos0 = blockIdx.x * 64;
    const int nE   = (E_CNT - pos0 < 64) ? (E_CNT - pos0) : 64;
    if (tid < 64) {
        int sl = (tid < nE) ? tid : (nE - 1);
        int e  = g_eid[pos0 + sl];
        Es[tid] = e; Ss[tid] = src[e]; Ds[tid] = dst[e];
    }
    __syncthreads();

    // ---- stage EMBh (transposed halves, *1/8), W1sh (dup half2), SHs(*w2s) ----
    const float w2s = 0.08838834764831845f;    // 1/sqrt(128)
#pragma unroll
    for (int it = 0; it < 4; it++) {           // EMB: 64 slots x 16 float4
        int li = tid + it * 256;
        int slot = li >> 4, f = li & 15;
        float4 v = *(const float4*)&edge_emb[(size_t)Es[slot] * 64 + f * 4];
        EMBh[(f * 4 + 0) * 72 + slot] = __float2half_rn(v.x * 0.125f);
        EMBh[(f * 4 + 1) * 72 + slot] = __float2half_rn(v.y * 0.125f);
        EMBh[(f * 4 + 2) * 72 + slot] = __float2half_rn(v.z * 0.125f);
        EMBh[(f * 4 + 3) * 72 + slot] = __float2half_rn(v.w * 0.125f);
    }
#pragma unroll
    for (int it = 0; it < 8; it++) {           // W1sh[k][n] = dup(W1[k][n])
        int li = tid + it * 256;
        int k = li >> 5, f = li & 31;
        float4 v = *(const float4*)&W1[(size_t)k * 128 + f * 4];
        *(uint4*)&W1sh[k * 128 + f * 4] = make_uint4(
            h2_bits(__float2half2_rn(v.x)),
            h2_bits(__float2half2_rn(v.y)),
            h2_bits(__float2half2_rn(v.z)),
            h2_bits(__float2half2_rn(v.w)));
    }
    {                                          // SHs: 64 x 4 float4, *w2s
        int slot = tid >> 2, j = tid & 3;
        float4 v = make_float4(0.f, 0.f, 0.f, 0.f);
        if (slot < nE) {
            v = *(const float4*)&edge_sh[(size_t)Es[slot] * 16 + j * 4];
            v.x *= w2s; v.y *= w2s; v.z *= w2s; v.w *= w2s;
        }
        *(float4*)&SHs[slot * 16 + j * 4] = v;
    }
    __syncthreads();

    // ---- GEMM1: Hsth = half2(silu(EMB @ W1)), 64x128x64, HFMA2 ----
    {
        float ax[4][4], ay[4][4];
#pragma unroll
        for (int p = 0; p < 4; p++)
#pragma unroll
            for (int j = 0; j < 4; j++) { ax[p][j] = 0.f; ay[p][j] = 0.f; }

#pragma unroll
        for (int kc = 0; kc < 64; kc += 8) {
            __half2 ah[4][4];
#pragma unroll
            for (int p = 0; p < 4; p++)
#pragma unroll
                for (int j = 0; j < 4; j++) ah[p][j] = __float2half2_rn(0.f);
#pragma unroll
            for (int kk = 0; kk < 8; kk++) {
                int k = kc + kk;
                uint4 bq = *(const uint4*)&W1sh[k * 128 + c0];
                __half2 b0 = *(__half2*)&bq.x, b1 = *(__half2*)&bq.y;
                __half2 b2 = *(__half2*)&bq.z, b3 = *(__half2*)&bq.w;
#pragma unroll
                for (int p = 0; p < 4; p++) {
                    u32 aw = EMBw[k * 36 + p0 + p];      // pair broadcast
                    __half2 ap = *(__half2*)&aw;
                    ah[p][0] = __hfma2(ap, b0, ah[p][0]);
                    ah[p][1] = __hfma2(ap, b1, ah[p][1]);
                    ah[p][2] = __hfma2(ap, b2, ah[p][2]);
                    ah[p][3] = __hfma2(ap, b3, ah[p][3]);
                }
            }
#pragma unroll
            for (int p = 0; p < 4; p++)
#pragma unroll
                for (int j = 0; j < 4; j++) {
                    float2 f = __half22float2(ah[p][j]);
                    ax[p][j] += f.x; ay[p][j] += f.y;
                }
        }
        // epilogue: silu -> half2 pair -> Hsth[c][pair]
#pragma unroll
        for (int p = 0; p < 4; p++)
#pragma unroll
            for (int j = 0; j < 4; j++) {
                __half2 hv = __floats2half2_rn(silu_f(ax[p][j]), silu_f(ay[p][j]));
                Hsth[(c0 + j) * 36 + p0 + p] = *(u32*)&hv;
            }
    }
    __syncthreads();   // Hsth ready; EMB(Ws) and W1sh(TPW) free

    // ---- per-l: GEMM2 (HFMA2) + fold x + run-length segment scatter ----
    for (int l = 0; l < 4; l++) {
        float ax[4][4], ay[4][4];
#pragma unroll
        for (int p = 0; p < 4; p++)
#pragma unroll
            for (int j = 0; j < 4; j++) { ax[p][j] = 0.f; ay[p][j] = 0.f; }

        for (int k0 = 0; k0 < 128; k0 += 64) {
            if (k0) __syncthreads();           // Wsh reuse guard within l
            // stage Wsh[k][n] = dup(W2[k0+k][l*128+n])  (w2s folded into SHs)
#pragma unroll
            for (int it = 0; it < 8; it++) {
                int li = tid + it * 256;
                int k = li >> 5, f = li & 31;
                float4 v = *(const float4*)&W2[(size_t)(k0 + k) * 512 + l * 128 + f * 4];
                *(uint4*)&Wsh[k * 128 + f * 4] = make_uint4(
                    h2_bits(__float2half2_rn(v.x)),
                    h2_bits(__float2half2_rn(v.y)),
                    h2_bits(__float2half2_rn(v.z)),
                    h2_bits(__float2half2_rn(v.w)));
            }
            __syncthreads();

#pragma unroll
            for (int kc = 0; kc < 64; kc += 8) {
                __half2 ah[4][4];
#pragma unroll
                for (int p = 0; p < 4; p++)
#pragma unroll
                    for (int j = 0; j < 4; j++) ah[p][j] = __float2half2_rn(0.f);
#pragma unroll
                for (int kk = 0; kk < 8; kk++) {
                    int k = kc + kk;
                    uint4 bq = *(const uint4*)&Wsh[k * 128 + c0];
                    __half2 b0 = *(__half2*)&bq.x, b1 = *(__half2*)&bq.y;
                    __half2 b2 = *(__half2*)&bq.z, b3 = *(__half2*)&bq.w;
#pragma unroll
                    for (int p = 0; p < 4; p++) {
                        u32 aw = Hsth[(k0 + k) * 36 + p0 + p];
                        __half2 ap = *(__half2*)&aw;
                        ah[p][0] = __hfma2(ap, b0, ah[p][0]);
                        ah[p][1] = __hfma2(ap, b1, ah[p][1]);
                        ah[p][2] = __hfma2(ap, b2, ah[p][2]);
                        ah[p][3] = __hfma2(ap, b3, ah[p][3]);
                    }
                }
#pragma unroll
                for (int p = 0; p < 4; p++)
#pragma unroll
                    for (int j = 0; j < 4; j++) {
                        float2 f = __half22float2(ah[p][j]);
                        ax[p][j] += f.x; ay[p][j] += f.y;
                    }
            }
        }
        __syncthreads();   // Wsh reads + previous TPW use complete

        // fold: TPW[row][c] = acc * x_src[src[row]][c]
#pragma unroll
        for (int p = 0; p < 4; p++) {
            int rA = r0 + 2 * p, rB = rA + 1;
            float4 xA = *(const float4*)&src_features[(size_t)Ss[rA] * 128 + c0];
            float4 xB = *(const float4*)&src_features[(size_t)Ss[rB] * 128 + c0];
            *(float4*)&TPW[rA * 128 + c0] =
                make_float4(ax[p][0] * xA.x, ax[p][1] * xA.y,
                            ax[p][2] * xA.z, ax[p][3] * xA.w);
            *(float4*)&TPW[rB * 128 + c0] =
                make_float4(ay[p][0] * xB.x, ay[p][1] * xB.y,
                            ay[p][2] * xB.z, ay[p][3] * xB.w);
        }
        __syncthreads();

        // scatter: run-length reduce over 64 dst-sorted edges
        {
            const int d    = 2 * l + 1;
            const int soff = l * l;
            const int ob   = (l == 0) ? 0 : (l == 1) ? 128 : (l == 2) ? 512 : 1152;
            const int ncol = 128 * d;
            for (int q = tid; q < ncol; q += 256) {
                const int c = q / d;
                const int s = q - c * d;
                float a = 0.f;
                int cur = Ds[0];
#pragma unroll 8
                for (int e = 0; e < 64; e++) {
                    int dn = Ds[e];
                    if (dn != cur) {
                        atomicAdd(&out[(size_t)cur * OUTC + ob + q], a);
                        a = 0.f; cur = dn;
                    }
                    a += TPW[e * 128 + c] * SHs[e * 16 + soff + s];
                }
                atomicAdd(&out[(size_t)cur * OUTC + ob + q], a);
            }
        }
        __syncthreads();
    }
}

// ---------------- launch ----------------
extern "C" void kernel_launch(void* const* d_in, const int* in_sizes, int n_in,
                              void* d_out, int out_size)
{
    const float* src_features = (const float*)d_in[0];
    const float* edge_sh      = (const float*)d_in[1];
    const float* edge_emb     = (const float*)d_in[2];
    const float* W1           = (const float*)d_in[3];
    const float* W2           = (const float*)d_in[4];
    const int*   src          = (const int*)d_in[5];
    const int*   dst          = (const int*)d_in[6];
    float*       out          = (float*)d_out;
    (void)in_sizes; (void)n_in; (void)out_size;

    static bool attr_done = false;
    if (!attr_done) {
        cudaFuncSetAttribute(fused_k, cudaFuncAttributeMaxDynamicSharedMemorySize,
                             SMEM_BYTES);
        attr_done = true;
    }

    // CSR build
    zero_cnt_k<<<(NDST + 255) / 256, 256>>>();
    hist_k<<<(E_CNT + 255) / 256, 256>>>(dst);
    scan_k<<<1, 1024>>>();
    fill_k<<<(E_CNT + 255) / 256, 256>>>(dst);

    // zero output (atomic accumulation target)
    const int n4 = NDST * OUTC / 4;
    zero_out_k<<<(n4 + 255) / 256, 256>>>((float4*)out, n4);

    // fused HFMA2 MLP + TP + scatter (64 edges/block, 2 CTAs/SM)
    const int nblk = (E_CNT + 63) / 64;
    fused_k<<<nblk, 256, SMEM_BYTES>>>(src_features, edge_sh, edge_emb,
                                       W1, W2, src, dst, out);
}

// round 17
// speedup vs baseline: 1.7022x; 1.0184x over previous
#include <cuda_runtime.h>
#include <cstdint>

typedef unsigned long long u64;

#define E_CNT 100000
#define NDST  10000
#define OUTC  2048
#define N4    (NDST * OUTC / 4)          // float4 count of output

// ---------------- small device scratch (CSR only) ----------------
// zero-initialized at module load; scan_k re-zeros g_counts every launch.
__device__ int g_counts[NDST];
__device__ int g_cursor[NDST];
__device__ int g_eid   [E_CNT];

// ---------------- prologue kernels ----------------
// one launch: every block zeroes its slice of out; blocks < 391 also histogram.
__global__ void histzero_k(const int* __restrict__ dst, float4* __restrict__ out) {
    int i = blockIdx.x * blockDim.x + threadIdx.x;
    if (i < N4) out[i] = make_float4(0.f, 0.f, 0.f, 0.f);
    if (i < E_CNT) atomicAdd(&g_counts[dst[i]], 1);
}
__global__ void scan_k() {
    __shared__ int ss[1024];
    const int tid = threadIdx.x;
    const int CH = 10;
    int base = tid * CH, loc[CH], s = 0;
#pragma unroll
    for (int i = 0; i < CH; i++) {
        int idx = base + i;
        int v = (idx < NDST) ? g_counts[idx] : 0;
        loc[i] = s; s += v;
    }
    ss[tid] = s; __syncthreads();
    for (int off = 1; off < 1024; off <<= 1) {
        int v = 0;
        if (tid >= off) v = ss[tid - off];
        __syncthreads();
        if (tid >= off) ss[tid] += v;
        __syncthreads();
    }
    int excl = (tid == 0) ? 0 : ss[tid - 1];
#pragma unroll
    for (int i = 0; i < CH; i++) {
        int idx = base + i;
        if (idx < NDST) {
            g_cursor[idx] = excl + loc[i];
            g_counts[idx] = 0;              // self-clean for next replay
        }
    }
}
__global__ void fill_k(const int* __restrict__ dst) {
    int e = blockIdx.x * blockDim.x + threadIdx.x;
    if (e < E_CNT) {
        int p = atomicAdd(&g_cursor[dst[e]], 1);
        g_eid[p] = e;
    }
}

// ---------------- packed fp32x2 helpers ----------------
__device__ __forceinline__ void ffma2(u64& d, u64 a, u64 b) {
    asm("fma.rn.f32x2 %0, %1, %2, %0;" : "+l"(d) : "l"(a), "l"(b));
}
__device__ __forceinline__ u64 pack2(float x) {
    u64 r; asm("mov.b64 %0, {%1, %1};" : "=l"(r) : "f"(x)); return r;
}
__device__ __forceinline__ u64 packf2(float lo, float hi) {
    u64 r; asm("mov.b64 %0, {%1, %2};" : "=l"(r) : "f"(lo), "f"(hi)); return r;
}
__device__ __forceinline__ float2 unpack2(u64 v) {
    float2 f; asm("mov.b64 {%0, %1}, %2;" : "=f"(f.x), "=f"(f.y) : "l"(v)); return f;
}
__device__ __forceinline__ float silu_f(float x) {
    return x / (1.f + __expf(-x));
}

// ---------------- smem layout (float offsets; exactly R10) ----------------
#define F_HST  0            // Hst [128][66]
#define F_WS   8448         // Ws [64][128] (EMBt [64][66] aliases)
#define F_W1S  16640        // W1s [64][128] (TPW aliases)
#define F_SHS  24832        // SHs [64][16]
#define F_END  25856
#define SMEM_BYTES ((F_END + 192) * 4)

// ---------------- fused kernel: FFMA2 MLP + TP + segment scatter -----------
// (byte-identical hot paths to the 426.6us R10 kernel)
__global__ __launch_bounds__(256, 2) void fused_k(
    const float* __restrict__ src_features,
    const float* __restrict__ edge_sh,
    const float* __restrict__ edge_emb,
    const float* __restrict__ W1,
    const float* __restrict__ W2,
    const int*   __restrict__ src,
    const int*   __restrict__ dst,
    float*       __restrict__ out)
{
    extern __shared__ float sm[];
    float* Hst  = sm + F_HST;
    float* Ws   = sm + F_WS;   float* EMBt = Ws;
    float* W1s  = sm + F_W1S;  float* TPW  = W1s;
    float* SHs  = sm + F_SHS;
    int*   Es   = (int*)(sm + F_END);
    int*   Ss   = Es + 64;
    int*   Ds   = Ss + 64;

    const int tid = threadIdx.x;
    const int tr  = tid >> 5;
    const int tc  = tid & 31;
    const int r0  = tr * 8;
    const int c0  = tc * 4;

    const int pos0 = blockIdx.x * 64;
    const int nE   = (E_CNT - pos0 < 64) ? (E_CNT - pos0) : 64;
    if (tid < 64) {
        int sl = (tid < nE) ? tid : (nE - 1);
        int e  = g_eid[pos0 + sl];
        Es[tid] = e; Ss[tid] = src[e]; Ds[tid] = dst[e];
    }
    __syncthreads();

#pragma unroll
    for (int it = 0; it < 4; it++) {
        int li = tid + it * 256;
        int slot = li >> 4, f = li & 15;
        float4 v = *(const float4*)&edge_emb[(size_t)Es[slot] * 64 + f * 4];
        EMBt[(f * 4 + 0) * 66 + slot] = v.x;
        EMBt[(f * 4 + 1) * 66 + slot] = v.y;
        EMBt[(f * 4 + 2) * 66 + slot] = v.z;
        EMBt[(f * 4 + 3) * 66 + slot] = v.w;
    }
#pragma unroll
    for (int it = 0; it < 8; it++) {
        int li = tid + it * 256;
        int k = li >> 5, f = li & 31;
        float4 v = *(const float4*)&W1[(size_t)k * 128 + f * 4];
        v.x *= 0.125f; v.y *= 0.125f; v.z *= 0.125f; v.w *= 0.125f;
        *(float4*)&W1s[k * 128 + f * 4] = v;
    }
    {
        int slot = tid >> 2, j = tid & 3;
        float4 v = make_float4(0.f, 0.f, 0.f, 0.f);
        if (slot < nE)
            v = *(const float4*)&edge_sh[(size_t)Es[slot] * 16 + j * 4];
        *(float4*)&SHs[slot * 16 + j * 4] = v;
    }
    __syncthreads();

    // ---- GEMM1: Hst = silu(EMB @ W1s)^T, 64x128x64, FFMA2 ----
    {
        u64 acc[4][4];
#pragma unroll
        for (int p = 0; p < 4; p++)
#pragma unroll
            for (int j = 0; j < 4; j++) acc[p][j] = 0ull;

#pragma unroll 8
        for (int kk = 0; kk < 64; kk++) {
            float4 rb = *(const float4*)&W1s[kk * 128 + c0];
            u64 bb0 = pack2(rb.x), bb1 = pack2(rb.y);
            u64 bb2 = pack2(rb.z), bb3 = pack2(rb.w);
#pragma unroll
            for (int p = 0; p < 4; p++) {
                u64 ap = *(const u64*)&EMBt[kk * 66 + r0 + 2 * p];
                ffma2(acc[p][0], ap, bb0); ffma2(acc[p][1], ap, bb1);
                ffma2(acc[p][2], ap, bb2); ffma2(acc[p][3], ap, bb3);
            }
        }
#pragma unroll
        for (int p = 0; p < 4; p++)
#pragma unroll
            for (int j = 0; j < 4; j++) {
                float2 v = unpack2(acc[p][j]);
                v.x = silu_f(v.x); v.y = silu_f(v.y);
                *(u64*)&Hst[(c0 + j) * 66 + r0 + 2 * p] = packf2(v.x, v.y);
            }
    }
    __syncthreads();

    // ---- per-l: GEMM2 (FFMA2) + fold x + run-length segment scatter ----
    const float w2s = 0.08838834764831845f;

    for (int l = 0; l < 4; l++) {
        u64 acc[4][4];
#pragma unroll
        for (int p = 0; p < 4; p++)
#pragma unroll
            for (int j = 0; j < 4; j++) acc[p][j] = 0ull;

        for (int k0 = 0; k0 < 128; k0 += 64) {
            if (k0) __syncthreads();
#pragma unroll
            for (int it = 0; it < 8; it++) {
                int li = tid + it * 256;
                int k = li >> 5, f = li & 31;
                float4 v = *(const float4*)&W2[(size_t)(k0 + k) * 512 + l * 128 + f * 4];
                v.x *= w2s; v.y *= w2s; v.z *= w2s; v.w *= w2s;
                *(float4*)&Ws[k * 128 + f * 4] = v;
            }
            __syncthreads();

#pragma unroll 8
            for (int kk = 0; kk < 64; kk++) {
                float4 rb = *(const float4*)&Ws[kk * 128 + c0];
                u64 bb0 = pack2(rb.x), bb1 = pack2(rb.y);
                u64 bb2 = pack2(rb.z), bb3 = pack2(rb.w);
#pragma unroll
                for (int p = 0; p < 4; p++) {
                    u64 ap = *(const u64*)&Hst[(k0 + kk) * 66 + r0 + 2 * p];
                    ffma2(acc[p][0], ap, bb0); ffma2(acc[p][1], ap, bb1);
                    ffma2(acc[p][2], ap, bb2); ffma2(acc[p][3], ap, bb3);
                }
            }
        }
        __syncthreads();

#pragma unroll
        for (int p = 0; p < 4; p++) {
            int rA = r0 + 2 * p, rB = rA + 1;
            float4 xA = *(const float4*)&src_features[(size_t)Ss[rA] * 128 + c0];
            float4 xB = *(const float4*)&src_features[(size_t)Ss[rB] * 128 + c0];
            float2 q0 = unpack2(acc[p][0]), q1 = unpack2(acc[p][1]);
            float2 q2 = unpack2(acc[p][2]), q3 = unpack2(acc[p][3]);
            *(float4*)&TPW[rA * 128 + c0] =
                make_float4(q0.x * xA.x, q1.x * xA.y, q2.x * xA.z, q3.x * xA.w);
            *(float4*)&TPW[rB * 128 + c0] =
                make_float4(q0.y * xB.x, q1.y * xB.y, q2.y * xB.z, q3.y * xB.w);
        }
        __syncthreads();

        {
            const int d    = 2 * l + 1;
            const int soff = l * l;
            const int ob   = (l == 0) ? 0 : (l == 1) ? 128 : (l == 2) ? 512 : 1152;
            const int ncol = 128 * d;
            for (int q = tid; q < ncol; q += 256) {
                const int c = q / d;
                const int s = q - c * d;
                float a = 0.f;
                int cur = Ds[0];
#pragma unroll 8
                for (int e = 0; e < 64; e++) {
                    int dn = Ds[e];
                    if (dn != cur) {
                        atomicAdd(&out[(size_t)cur * OUTC + ob + q], a);
                        a = 0.f; cur = dn;
                    }
                    a += TPW[e * 128 + c] * SHs[e * 16 + soff + s];
                }
                atomicAdd(&out[(size_t)cur * OUTC + ob + q], a);
            }
        }
        __syncthreads();
    }
}

// ---------------- launch ----------------
extern "C" void kernel_launch(void* const* d_in, const int* in_sizes, int n_in,
                              void* d_out, int out_size)
{
    const float* src_features = (const float*)d_in[0];
    const float* edge_sh      = (const float*)d_in[1];
    const float* edge_emb     = (const float*)d_in[2];
    const float* W1           = (const float*)d_in[3];
    const float* W2           = (const float*)d_in[4];
    const int*   src          = (const int*)d_in[5];
    const int*   dst          = (const int*)d_in[6];
    float*       out          = (float*)d_out;
    (void)in_sizes; (void)n_in; (void)out_size;

    static bool attr_done = false;
    if (!attr_done) {
        cudaFuncSetAttribute(fused_k, cudaFuncAttributeMaxDynamicSharedMemorySize,
                             SMEM_BYTES);
        attr_done = true;
    }

    // fused output-zeroing + dst histogram (g_counts zeroed by prior scan_k,
    // or by static zero-init on the very first launch)
    histzero_k<<<(N4 + 255) / 256, 256>>>(dst, (float4*)out);
    scan_k<<<1, 1024>>>();
    fill_k<<<(E_CNT + 255) / 256, 256>>>(dst);

    // fused FFMA2 MLP + TP + scatter (64 edges/block, 2 CTAs/SM)
    const int nblk = (E_CNT + 63) / 64;
    fused_k<<<nblk, 256, SMEM_BYTES>>>(src_features, edge_sh, edge_emb,
                                       W1, W2, src, dst, out);
}